// round 8
// baseline (speedup 1.0000x reference)
#include <cuda_runtime.h>
#include <math.h>

#define N_EDGES   800000
#define N_NODES   50000
#define D_FEAT    128
#define NEG_SLOPE 0.2f
#define N_GROUPS  (N_EDGES / 4)     // 200000 groups of 4 edges

// Scratch (zero-init at module load; k_recip_clear re-zeros d_seg_sum
// each run so every graph replay starts clean).
__device__ float d_seg_sum[N_NODES];
__device__ float d_seg_rcp[N_NODES];

// ---------------------------------------------------------------------------
// K1: grid-stride, double-buffered. One warp per group of 4 edges:
// each lane loads one float4 per edge (32*4 = 128 = D_FEAT).
// Next group's loads are issued BEFORE the current group's reduction,
// so DRAM requests stay in flight through the compute phase.
// ---------------------------------------------------------------------------
__global__ __launch_bounds__(256) void k_logits(
    const float* __restrict__ x,
    const float* __restrict__ W,
    const float* __restrict__ b,
    const int*   __restrict__ index,   // int32 (jax x64 disabled)
    float* __restrict__ out)
{
    const unsigned lane = threadIdx.x & 31;
    const int warp   = blockIdx.x * (blockDim.x >> 5) + (threadIdx.x >> 5);
    const int nwarps = gridDim.x * (blockDim.x >> 5);

    const float4 wv = *reinterpret_cast<const float4*>(W + lane * 4);
    const float  bias = b[0];

    int g = warp;
    if (g >= N_GROUPS) return;

    // Prologue: load group g
    const float4* xp = reinterpret_cast<const float4*>(x) + (long long)g * 128 + lane;
    float4 x0 = __ldcs(xp +  0);
    float4 x1 = __ldcs(xp + 32);
    float4 x2 = __ldcs(xp + 64);
    float4 x3 = __ldcs(xp + 96);

    while (true) {
        const int gn = g + nwarps;
        float4 y0, y1, y2, y3;
        const bool more = (gn < N_GROUPS);
        if (more) {
            // Prefetch next group's rows (independent of everything below)
            const float4* yp = reinterpret_cast<const float4*>(x) + (long long)gn * 128 + lane;
            y0 = __ldcs(yp +  0);
            y1 = __ldcs(yp + 32);
            y2 = __ldcs(yp + 64);
            y3 = __ldcs(yp + 96);
        }

        // Per-edge dot partials
        float acc0 = fmaf(x0.x, wv.x, fmaf(x0.y, wv.y, fmaf(x0.z, wv.z, x0.w * wv.w)));
        float acc1 = fmaf(x1.x, wv.x, fmaf(x1.y, wv.y, fmaf(x1.z, wv.z, x1.w * wv.w)));
        float acc2 = fmaf(x2.x, wv.x, fmaf(x2.y, wv.y, fmaf(x2.z, wv.z, x2.w * wv.w)));
        float acc3 = fmaf(x3.x, wv.x, fmaf(x3.y, wv.y, fmaf(x3.z, wv.z, x3.w * wv.w)));

        // Multi-value warp reduce: interleave 4 edge-partials across lane&3,
        // then 3 butterfly rounds. 6 SHFL total instead of 20.
        // Round 1 (mask 1): s0 even->edge0, odd->edge1; s1 even->edge2, odd->edge3
        float t0 = (lane & 1) ? acc0 : acc1;
        float s0 = (lane & 1) ? acc1 : acc0;
        s0 += __shfl_xor_sync(0xffffffffu, t0, 1);
        float t1 = (lane & 1) ? acc2 : acc3;
        float s1 = (lane & 1) ? acc3 : acc2;
        s1 += __shfl_xor_sync(0xffffffffu, t1, 1);
        // Round 2 (mask 2): s2 at lane&3 == e holds edge-e partial
        float t2 = (lane & 2) ? s0 : s1;
        float s2 = (lane & 2) ? s1 : s0;
        s2 += __shfl_xor_sync(0xffffffffu, t2, 2);
        // Butterfly over the 8 replicas
        s2 += __shfl_xor_sync(0xffffffffu, s2, 4);
        s2 += __shfl_xor_sync(0xffffffffu, s2, 8);
        s2 += __shfl_xor_sync(0xffffffffu, s2, 16);

        if (lane < 4) {
            const int e = g * 4 + (int)lane;
            float r = s2 + bias;
            r = (r >= 0.0f) ? r : NEG_SLOPE * r;
            const float ex = expf(r);
            out[e] = ex;
            atomicAdd(&d_seg_sum[index[e]], ex);
        }

        if (!more) break;
        x0 = y0; x1 = y1; x2 = y2; x3 = y3;
        g = gn;
    }
}

// ---------------------------------------------------------------------------
// K2: d_seg_rcp <- 1/d_seg_sum, and re-zero d_seg_sum for the next replay.
// ---------------------------------------------------------------------------
__global__ void k_recip_clear() {
    int i = blockIdx.x * blockDim.x + threadIdx.x;
    if (i < N_NODES) {
        float s = d_seg_sum[i];
        d_seg_rcp[i] = (s > 0.0f) ? (1.0f / s) : 0.0f;
        d_seg_sum[i] = 0.0f;
    }
}

// ---------------------------------------------------------------------------
// K3: out[e] *= seg_rcp[index[e]], 4 edges/thread (vector loads, MLP>=4).
// ---------------------------------------------------------------------------
__global__ __launch_bounds__(256) void k_norm4(
    const int* __restrict__ index,
    float* __restrict__ out)
{
    const int t = blockIdx.x * blockDim.x + threadIdx.x;
    const int e4 = t * 4;
    if (e4 >= N_EDGES) return;

    int4   idx = *reinterpret_cast<const int4*>(index + e4);
    float4 o   = *reinterpret_cast<const float4*>(out + e4);

    float r0 = __ldg(&d_seg_rcp[idx.x]);
    float r1 = __ldg(&d_seg_rcp[idx.y]);
    float r2 = __ldg(&d_seg_rcp[idx.z]);
    float r3 = __ldg(&d_seg_rcp[idx.w]);

    o.x *= r0; o.y *= r1; o.z *= r2; o.w *= r3;
    *reinterpret_cast<float4*>(out + e4) = o;
}

// ---------------------------------------------------------------------------
extern "C" void kernel_launch(void* const* d_in, const int* in_sizes, int n_in,
                              void* d_out, int out_size) {
    const float* x     = (const float*)d_in[0];  // [800000, 128] f32
    const float* W     = (const float*)d_in[1];  // [128, 1] f32
    const float* b     = (const float*)d_in[2];  // [1] f32
    const int*   index = (const int*)d_in[3];    // [800000] int32
    float* out = (float*)d_out;                  // [800000] f32

    (void)in_sizes; (void)n_in; (void)out_size;

    // K1: persistent-ish grid: 4 CTAs/SM * 148 SMs, 8 warps each.
    const int nblk = 148 * 4;   // 592 CTAs -> 4736 warps, ~42 groups/warp
    k_logits<<<nblk, 256>>>(x, W, b, index, out);

    // K2: reciprocal + clear accumulators for next replay
    k_recip_clear<<<(N_NODES + 255) / 256, 256>>>();

    // K3: normalize, 4 edges/thread
    k_norm4<<<(N_EDGES / 4 + 255) / 256, 256>>>(index, out);
}

// round 11
// speedup vs baseline: 1.0306x; 1.0306x over previous
#include <cuda_runtime.h>
#include <math.h>

#define N_EDGES   800000
#define N_NODES   50000
#define D_FEAT    128
#define NEG_SLOPE 0.2f
#define N_GROUPS  (N_EDGES / 4)     // 200000 groups of 4 edges

// Scratch (zero-init at module load; k_recip_clear re-zeros d_seg_sum
// each run so every graph replay starts clean).
__device__ float d_seg_sum[N_NODES];
__device__ float d_seg_rcp[N_NODES];

// ---------------------------------------------------------------------------
// K1: grid-stride, double-buffered. One warp per group of 4 edges:
// each lane loads one float4 per edge (32*4 = 128 = D_FEAT).
// Next group's loads are issued BEFORE the current group's reduction.
// ---------------------------------------------------------------------------
__global__ __launch_bounds__(256) void k_logits(
    const float* __restrict__ x,
    const float* __restrict__ W,
    const float* __restrict__ b,
    const int*   __restrict__ index,   // int32 (jax x64 disabled)
    float* __restrict__ out)
{
    const unsigned lane = threadIdx.x & 31;
    const int warp   = blockIdx.x * (blockDim.x >> 5) + (threadIdx.x >> 5);
    const int nwarps = gridDim.x * (blockDim.x >> 5);

    const float4 wv = *reinterpret_cast<const float4*>(W + lane * 4);
    const float  bias = b[0];

    int g = warp;
    if (g >= N_GROUPS) return;

    // Prologue: load group g
    const float4* xp = reinterpret_cast<const float4*>(x) + (long long)g * 128 + lane;
    float4 x0 = __ldcs(xp +  0);
    float4 x1 = __ldcs(xp + 32);
    float4 x2 = __ldcs(xp + 64);
    float4 x3 = __ldcs(xp + 96);

    while (true) {
        const int gn = g + nwarps;
        float4 y0, y1, y2, y3;
        const bool more = (gn < N_GROUPS);
        if (more) {
            const float4* yp = reinterpret_cast<const float4*>(x) + (long long)gn * 128 + lane;
            y0 = __ldcs(yp +  0);
            y1 = __ldcs(yp + 32);
            y2 = __ldcs(yp + 64);
            y3 = __ldcs(yp + 96);
        }

        float acc0 = fmaf(x0.x, wv.x, fmaf(x0.y, wv.y, fmaf(x0.z, wv.z, x0.w * wv.w)));
        float acc1 = fmaf(x1.x, wv.x, fmaf(x1.y, wv.y, fmaf(x1.z, wv.z, x1.w * wv.w)));
        float acc2 = fmaf(x2.x, wv.x, fmaf(x2.y, wv.y, fmaf(x2.z, wv.z, x2.w * wv.w)));
        float acc3 = fmaf(x3.x, wv.x, fmaf(x3.y, wv.y, fmaf(x3.z, wv.z, x3.w * wv.w)));

        // Multi-value warp reduce: 6 SHFL for 4 sums.
        float t0 = (lane & 1) ? acc0 : acc1;
        float s0 = (lane & 1) ? acc1 : acc0;
        s0 += __shfl_xor_sync(0xffffffffu, t0, 1);
        float t1 = (lane & 1) ? acc2 : acc3;
        float s1 = (lane & 1) ? acc3 : acc2;
        s1 += __shfl_xor_sync(0xffffffffu, t1, 1);
        float t2 = (lane & 2) ? s0 : s1;
        float s2 = (lane & 2) ? s1 : s0;
        s2 += __shfl_xor_sync(0xffffffffu, t2, 2);
        s2 += __shfl_xor_sync(0xffffffffu, s2, 4);
        s2 += __shfl_xor_sync(0xffffffffu, s2, 8);
        s2 += __shfl_xor_sync(0xffffffffu, s2, 16);

        if (lane < 4) {
            const int e = g * 4 + (int)lane;
            float r = s2 + bias;
            r = (r >= 0.0f) ? r : NEG_SLOPE * r;
            const float ex = __expf(r);
            out[e] = ex;
            atomicAdd(&d_seg_sum[index[e]], ex);
        }

        if (!more) break;
        x0 = y0; x1 = y1; x2 = y2; x3 = y3;
        g = gn;
    }
}

// ---------------------------------------------------------------------------
// K2: d_seg_rcp <- 1/d_seg_sum, and re-zero d_seg_sum for the next replay.
// ---------------------------------------------------------------------------
__global__ void k_recip_clear() {
    int i = blockIdx.x * blockDim.x + threadIdx.x;
    if (i < N_NODES) {
        float s = d_seg_sum[i];
        d_seg_rcp[i] = (s > 0.0f) ? (1.0f / s) : 0.0f;
        d_seg_sum[i] = 0.0f;
    }
}

// ---------------------------------------------------------------------------
// K3: out[e] *= seg_rcp[index[e]], 8 edges per thread (two int4/float4
// pairs, 8 independent L2 gathers in flight). N_EDGES % 8 == 0.
// ---------------------------------------------------------------------------
__global__ __launch_bounds__(256) void k_norm8(
    const int* __restrict__ index,
    float* __restrict__ out)
{
    const int t = blockIdx.x * blockDim.x + threadIdx.x;
    const int e8 = t * 8;
    if (e8 >= N_EDGES) return;

    int4   ia = *reinterpret_cast<const int4*>(index + e8);
    int4   ib = *reinterpret_cast<const int4*>(index + e8 + 4);
    float4 oa = __ldcs(reinterpret_cast<const float4*>(out + e8));
    float4 ob = __ldcs(reinterpret_cast<const float4*>(out + e8 + 4));

    float r0 = __ldg(&d_seg_rcp[ia.x]);
    float r1 = __ldg(&d_seg_rcp[ia.y]);
    float r2 = __ldg(&d_seg_rcp[ia.z]);
    float r3 = __ldg(&d_seg_rcp[ia.w]);
    float r4 = __ldg(&d_seg_rcp[ib.x]);
    float r5 = __ldg(&d_seg_rcp[ib.y]);
    float r6 = __ldg(&d_seg_rcp[ib.z]);
    float r7 = __ldg(&d_seg_rcp[ib.w]);

    oa.x *= r0; oa.y *= r1; oa.z *= r2; oa.w *= r3;
    ob.x *= r4; ob.y *= r5; ob.z *= r6; ob.w *= r7;
    *reinterpret_cast<float4*>(out + e8)     = oa;
    *reinterpret_cast<float4*>(out + e8 + 4) = ob;
}

// ---------------------------------------------------------------------------
extern "C" void kernel_launch(void* const* d_in, const int* in_sizes, int n_in,
                              void* d_out, int out_size) {
    const float* x     = (const float*)d_in[0];  // [800000, 128] f32
    const float* W     = (const float*)d_in[1];  // [128, 1] f32
    const float* b     = (const float*)d_in[2];  // [1] f32
    const int*   index = (const int*)d_in[3];    // [800000] int32
    float* out = (float*)d_out;                  // [800000] f32

    (void)in_sizes; (void)n_in; (void)out_size;

    // K1: 5 CTAs/SM (regs=47 -> 65536/(256*47) = 5), 148 SMs.
    const int nblk = 148 * 5;   // 740 CTAs -> 5920 warps
    k_logits<<<nblk, 256>>>(x, W, b, index, out);

    // K2: reciprocal + clear accumulators for next replay
    k_recip_clear<<<(N_NODES + 255) / 256, 256>>>();

    // K3: normalize, 8 edges/thread -> 100k threads
    k_norm8<<<(N_EDGES / 8 + 255) / 256, 256>>>(index, out);
}